// round 9
// baseline (speedup 1.0000x reference)
#include <cuda_runtime.h>
#include <cstdint>
#include <cstddef>

// Problem constants
#define BB   32
#define TT   4096
#define DD   512
#define GG   8
#define OUTD 512

#define NCHUNK 16           // partial slots per b (one per block)
#define CHUNK  128          // tokens per scan pass
#define PASSES 2            // chunks per block (256 tokens total)

// K3 tiling: one-shot tiles, split-K over 16 d-tiles of 32
#define K3B   32            // o-tile width
#define K3D   32            // d-tile depth
#define K3_ND (DD / K3D)    // 16
#define MP3   36            // mean smem pitch (floats)

// -------- device scratch (no allocations allowed) --------
__device__ int   g_idx[TT];                               // token indices sorted by type
__device__ int   g_segstart[GG + 1];                      // group segment boundaries
__device__ float g_part[(size_t)BB * GG * NCHUNK * DD];   // partial sums [b][g][c][d] (8.4 MB)
__device__ float g_pcnt[BB * GG * NCHUNK];                // partial counts [b][g][c]
__device__ float g_means[(size_t)GG * BB * DD];           // means [g][b][d] (0.5 MB)
__device__ float g_ppart[(size_t)K3_ND * BB * GG * OUTD]; // gemm partials [dq][b][g][o] (8 MB)

// =====================================================================
// K1: deterministic stable counting sort of token_types (1 block, 512 thr)
// =====================================================================
__global__ void __launch_bounds__(512) k_sort(const int* __restrict__ types) {
    __shared__ int s[GG][512];
    __shared__ int base_s[GG + 1];
    const int tid = threadIdx.x;

    int ty[8];
    int lc[GG];
#pragma unroll
    for (int g = 0; g < GG; g++) lc[g] = 0;
#pragma unroll
    for (int k = 0; k < 8; k++) {
        const int t  = tid * 8 + k;
        const int tt = types[t];
        ty[k] = tt;
#pragma unroll
        for (int g = 0; g < GG; g++) lc[g] += (tt == g);
    }
#pragma unroll
    for (int g = 0; g < GG; g++) s[g][tid] = lc[g];
    __syncthreads();

    for (int off = 1; off < 512; off <<= 1) {
        int add[GG];
#pragma unroll
        for (int g = 0; g < GG; g++) add[g] = (tid >= off) ? s[g][tid - off] : 0;
        __syncthreads();
#pragma unroll
        for (int g = 0; g < GG; g++) s[g][tid] += add[g];
        __syncthreads();
    }

    if (tid == 0) {
        int b0 = 0;
        for (int g = 0; g < GG; g++) {
            base_s[g] = b0;
            g_segstart[g] = b0;
            b0 += s[g][511];
        }
        base_s[GG] = b0;
        g_segstart[GG] = b0;
    }
    __syncthreads();

    int cur[GG];
#pragma unroll
    for (int g = 0; g < GG; g++) cur[g] = base_s[g] + s[g][tid] - lc[g];
#pragma unroll
    for (int k = 0; k < 8; k++) {
        const int t  = tid * 8 + k;
        const int tt = ty[k];
#pragma unroll
        for (int g = 0; g < GG; g++) {
            if (tt == g) { g_idx[cur[g]] = t; cur[g]++; }
        }
    }
}

// =====================================================================
// K2: segmented partial sums, valid-token compaction, 2 chunks per block.
// Grid (B=32, NCHUNK=16) = 512 blocks, 128 thr.
// Persistent acc across both chunks -> half the partial traffic of R6.
// =====================================================================
__global__ void __launch_bounds__(128, 8) k_partial(const float* __restrict__ batch,
                                                    const int* __restrict__ mask) {
    __shared__ int t_c[CHUNK];          // compacted valid token ids
    __shared__ int scan_s[CHUNK + 1];   // exclusive scan of valid flags
    __shared__ int seg_s[GG + 1];       // global segment bounds
    __shared__ int segc_s[GG + 1];      // compacted local segment bounds
    __shared__ int wsum_s[4];           // per-warp scan totals

    const int tid = threadIdx.x;
    const int b   = blockIdx.x;
    const int c   = blockIdx.y;

    if (tid < GG + 1) seg_s[tid] = g_segstart[tid];

    float4 acc[GG];
#pragma unroll
    for (int g = 0; g < GG; g++) acc[g] = make_float4(0.f, 0.f, 0.f, 0.f);
    int cnt_acc = 0;   // valid count for group `tid` (tid < GG only)

    const float* bb = batch + (size_t)b * TT * DD + tid * 4;

    for (int h = 0; h < PASSES; h++) {
        const int c0 = (c * PASSES + h) * CHUNK;
        __syncthreads();   // protect smem reuse across passes

        // ---- stage + block-wide compaction scan ----
        const int t = g_idx[c0 + tid];
        const int v = mask[b * TT + t] ? 0 : 1;   // int32 bool: nonzero = padded

        const int lane = tid & 31;
        const int w    = tid >> 5;
        int x = v;
#pragma unroll
        for (int off = 1; off < 32; off <<= 1) {
            const int y = __shfl_up_sync(0xffffffffu, x, off);
            if (lane >= off) x += y;
        }
        if (lane == 31) wsum_s[w] = x;
        __syncthreads();
        int woff = 0;
#pragma unroll
        for (int i = 0; i < 4; i++) woff += (i < w) ? wsum_s[i] : 0;
        const int incl = x + woff;
        scan_s[tid + 1] = incl;
        if (tid == 0) scan_s[0] = 0;
        __syncthreads();
        if (v) t_c[incl - 1] = t;
        if (tid < GG + 1) {
            int lo = seg_s[tid] - c0;
            lo = lo < 0 ? 0 : (lo > CHUNK ? CHUNK : lo);
            segc_s[tid] = scan_s[lo];
        }
        __syncthreads();

        if (tid < GG) cnt_acc += segc_s[tid + 1] - segc_s[tid];

        // ---- hot loop: only valid tokens, streaming float4 loads ----
#pragma unroll
        for (int g = 0; g < GG; g++) {
            const int jlo = segc_s[g];
            const int jhi = segc_s[g + 1];
#pragma unroll 8
            for (int j = jlo; j < jhi; j++) {
                const int tt2 = t_c[j];
                const float4 v4 = __ldcs((const float4*)(bb + (size_t)tt2 * DD));
                acc[g].x += v4.x; acc[g].y += v4.y; acc[g].z += v4.z; acc[g].w += v4.w;
            }
        }
    }

#pragma unroll
    for (int g = 0; g < GG; g++)
        *(float4*)&g_part[(((size_t)b * GG + g) * NCHUNK + c) * DD + tid * 4] = acc[g];
    if (tid < GG)
        g_pcnt[(b * GG + tid) * NCHUNK + c] = (float)cnt_acc;
}

// =====================================================================
// K2.5: reduce partials -> means [g][b][d]. Grid (B, G) = 256 blocks, 128 thr.
// =====================================================================
__global__ void __launch_bounds__(128) k_means() {
    const int b = blockIdx.x, g = blockIdx.y, tid = threadIdx.x;

    const size_t base = ((size_t)b * GG + g) * NCHUNK;
    float4 s = make_float4(0.f, 0.f, 0.f, 0.f);
    float  cnt = 0.f;
#pragma unroll
    for (int c = 0; c < NCHUNK; c++) {
        const float4 p = __ldcs((const float4*)&g_part[(base + c) * DD + tid * 4]);
        s.x += p.x; s.y += p.y; s.z += p.z; s.w += p.w;
        cnt += g_pcnt[base + c];
    }
    const float inv = (cnt > 0.f) ? (1.0f / cnt) : 0.0f;
    s.x *= inv; s.y *= inv; s.z *= inv; s.w *= inv;
    *(float4*)&g_means[((size_t)g * BB + b) * DD + tid * 4] = s;
}

// =====================================================================
// K3: split-K GEMM. Grid (G=8, 16 o-tiles, 16 d-tiles) = 2048 blocks, 128 thr.
// Each block: 32x32 W tile + 32x32 mean tile loaded once, 256 FFMA/thread.
// =====================================================================
__global__ void __launch_bounds__(128, 12) k_gemm3(const float* __restrict__ Wt) {
    __shared__ __align__(16) float w_s[K3D * K3B];     // 32 x 32 = 4 KB
    __shared__ __align__(16) float mean_s[BB * MP3];   // 32 x 32 (pitch 36) = 4.6 KB

    const int tid   = threadIdx.x;
    const int g     = blockIdx.x;
    const int obase = blockIdx.y * K3B;
    const int dbase = blockIdx.z * K3D;

    const float* msrc = &g_means[(size_t)g * BB * DD + dbase];
    const float* wsrc = Wt + ((size_t)g * DD + dbase) * OUTD + obase;

#pragma unroll
    for (int k = 0; k < 2; k++) {
        const int i   = tid + k * 128;
        const int row = i >> 3;            // 8 float4 per 32-col row
        const int col = (i & 7) * 4;
        const float4 v = *(const float4*)(wsrc + (size_t)row * OUTD + col);
        *(float4*)&w_s[row * K3B + col] = v;
    }
#pragma unroll
    for (int k = 0; k < 2; k++) {
        const int i  = tid + k * 128;
        const int bi = i >> 3;             // 8 float4 per 32-float row
        const int du = (i & 7) * 4;
        const float4 v = *(const float4*)(msrc + (size_t)bi * DD + du);
        *(float4*)&mean_s[bi * MP3 + du] = v;
    }
    __syncthreads();

    const int olane = (tid & 7) * 4;       // 8 lanes x float4 = 32 cols
    const int brow  = (tid >> 3) * 2;      // 16 x 2 = 32 rows

    const float* m0 = &mean_s[brow * MP3];
    const float* m1 = m0 + MP3;

    float4 a0 = make_float4(0.f, 0.f, 0.f, 0.f);
    float4 a1 = make_float4(0.f, 0.f, 0.f, 0.f);

#pragma unroll
    for (int d = 0; d < K3D; d++) {
        const float4 w4 = *(const float4*)&w_s[d * K3B + olane];
        const float  x0 = m0[d];
        const float  x1 = m1[d];
        a0.x = fmaf(x0, w4.x, a0.x); a0.y = fmaf(x0, w4.y, a0.y);
        a0.z = fmaf(x0, w4.z, a0.z); a0.w = fmaf(x0, w4.w, a0.w);
        a1.x = fmaf(x1, w4.x, a1.x); a1.y = fmaf(x1, w4.y, a1.y);
        a1.z = fmaf(x1, w4.z, a1.z); a1.w = fmaf(x1, w4.w, a1.w);
    }

    const int dq = blockIdx.z;
    const int o  = obase + olane;
    *(float4*)&g_ppart[(((size_t)dq * BB + brow)     * GG + g) * OUTD + o] = a0;
    *(float4*)&g_ppart[(((size_t)dq * BB + brow + 1) * GG + g) * OUTD + o] = a1;
}

// =====================================================================
// K4: reduce split-K partials + bias -> out. Grid (B, G) = 256 blocks.
// =====================================================================
__global__ void __launch_bounds__(128) k_out(const float* __restrict__ bias,
                                             float* __restrict__ out) {
    const int b = blockIdx.x, g = blockIdx.y, tid = threadIdx.x;
    const int o = tid * 4;

    float4 s = *(const float4*)(bias + g * OUTD + o);
#pragma unroll
    for (int dq = 0; dq < K3_ND; dq++) {
        const float4 p = __ldcs((const float4*)&g_ppart[(((size_t)dq * BB + b) * GG + g) * OUTD + o]);
        s.x += p.x; s.y += p.y; s.z += p.z; s.w += p.w;
    }
    *(float4*)(out + ((size_t)b * GG + g) * OUTD + o) = s;
}

// =====================================================================
// Launch
// =====================================================================
extern "C" void kernel_launch(void* const* d_in, const int* in_sizes, int n_in,
                              void* d_out, int out_size) {
    const float* batch = (const float*)d_in[0];
    const float* Wt    = (const float*)d_in[1];
    const float* bias  = (const float*)d_in[2];
    const int*   types = (const int*)d_in[3];
    const int*   mask  = (const int*)d_in[4];   // bool upcast to int32: nonzero = padded
    float*       out   = (float*)d_out;

    (void)in_sizes; (void)n_in; (void)out_size;

    k_sort<<<1, 512>>>(types);
    k_partial<<<dim3(BB, NCHUNK), 128>>>(batch, mask);
    k_means<<<dim3(BB, GG), 128>>>();
    k_gemm3<<<dim3(GG, OUTD / K3B, K3_ND), 128>>>(Wt);
    k_out<<<dim3(BB, GG), 128>>>(bias, out);
}

// round 11
// speedup vs baseline: 1.3316x; 1.3316x over previous
#include <cuda_runtime.h>
#include <cstdint>
#include <cstddef>

// Problem constants
#define BB   32
#define TT   4096
#define DD   512
#define GG   8
#define OUTD 512

#define NCHUNK 32
#define CHUNK  128          // tokens per (b,c) chunk == blockDim

// K3 tiling: split-K, o-tile 64, d-tile 32, thread = 4b x 4o
#define K3O   64
#define K3D   32
#define K3_ND (DD / K3D)    // 16
#define MP3   36            // mean smem pitch (floats); 144 B = 16B multiple

// -------- device scratch (no allocations allowed) --------
__device__ float g_part[(size_t)BB * GG * NCHUNK * DD];   // partial sums [b][g][c][d] (16 MB)
__device__ float g_pcnt[BB * GG * NCHUNK];                // partial counts [b][g][c]
__device__ float g_means[(size_t)GG * BB * DD];           // means [g][b][d] (0.5 MB)
__device__ float g_ppart[(size_t)K3_ND * BB * GG * OUTD]; // gemm partials [dq][b][g][o] (8 MB)

// =====================================================================
// K2: segmented partial sums with IN-BLOCK counting sort by (type, valid).
// Grid (B=32, NCHUNK=32) = 1024 blocks, 128 thr.
// Deterministic: scatter rank = (group, warp, lane); ascending t in group.
// =====================================================================
__global__ void __launch_bounds__(128, 8) k_partial(const float* __restrict__ batch,
                                                    const int* __restrict__ mask,
                                                    const int* __restrict__ types) {
    __shared__ int t_c[CHUNK];          // token ids grouped by type (valid only)
    __shared__ int cnt_s[33];           // (g-major, warp) counts -> prefix
    __shared__ int excl_s[32];          // exclusive offsets per (g, w)
    __shared__ int segc_s[GG + 1];      // group segment bounds (clamped)

    const int tid  = threadIdx.x;
    const int b    = blockIdx.x;
    const int c    = blockIdx.y;
    const int c0   = c * CHUNK;
    const int lane = tid & 31;
    const int w    = tid >> 5;

    const int t     = c0 + tid;
    const int gid   = types[t];                   // coalesced, 0..G-1
    const int valid = (mask[b * TT + t] == 0);    // coalesced; nonzero = padded

    t_c[tid] = t;                                 // defensive prefill (in-range)

    // ---- per-warp 8-way histogram via ballots ----
    int rank_in_warp = 0;
    const unsigned lt = (1u << lane) - 1u;
#pragma unroll
    for (int g = 0; g < GG; g++) {
        const unsigned bal = __ballot_sync(0xffffffffu, valid && (gid == g));
        if (gid == g) rank_in_warp = __popc(bal & lt);
        if (lane == g) cnt_s[g * 4 + w + 1] = __popc(bal);   // g-major slot
    }
    if (tid == 0) cnt_s[0] = 0;
    __syncthreads();

    // ---- single-thread 32-element prefix (trivially safe, ~32 cycles) ----
    if (tid == 0) {
        int run = 0;
#pragma unroll
        for (int i = 0; i < 32; i++) {
            excl_s[i] = run;
            run += cnt_s[i + 1];
            cnt_s[i + 1] = run;
        }
#pragma unroll
        for (int g = 0; g <= GG; g++) {
            int v = cnt_s[g * 4];
            segc_s[g] = v < 0 ? 0 : (v > CHUNK ? CHUNK : v);
        }
    }
    __syncthreads();

    // ---- scatter valid tokens grouped by type ----
    if (valid) {
        int pos = excl_s[gid * 4 + w] + rank_in_warp;
        if (pos >= 0 && pos < CHUNK) t_c[pos] = t;
    }
    __syncthreads();

    if (tid < GG)
        g_pcnt[(b * GG + tid) * NCHUNK + c] = (float)(segc_s[tid + 1] - segc_s[tid]);

    // ---- hot loop: only valid tokens, streaming float4 loads, pure adds ----
    float4 acc[GG];
#pragma unroll
    for (int g = 0; g < GG; g++) acc[g] = make_float4(0.f, 0.f, 0.f, 0.f);

    const float* bb = batch + (size_t)b * TT * DD + tid * 4;

#pragma unroll
    for (int g = 0; g < GG; g++) {
        const int jlo = segc_s[g];
        const int jhi = segc_s[g + 1];
#pragma unroll 8
        for (int j = jlo; j < jhi; j++) {
            const int tt2 = t_c[j];
            const float4 v4 = __ldcs((const float4*)(bb + (size_t)tt2 * DD));
            acc[g].x += v4.x; acc[g].y += v4.y; acc[g].z += v4.z; acc[g].w += v4.w;
        }
    }

#pragma unroll
    for (int g = 0; g < GG; g++)
        *(float4*)&g_part[(((size_t)b * GG + g) * NCHUNK + c) * DD + tid * 4] = acc[g];
}

// =====================================================================
// K2.5: reduce partials -> means [g][b][d]. Grid (B, G) = 256 blocks, 128 thr.
// =====================================================================
__global__ void __launch_bounds__(128) k_means() {
    const int b = blockIdx.x, g = blockIdx.y, tid = threadIdx.x;

    const size_t base = ((size_t)b * GG + g) * NCHUNK;
    float4 s = make_float4(0.f, 0.f, 0.f, 0.f);
    float  cnt = 0.f;
#pragma unroll 8
    for (int c = 0; c < NCHUNK; c++) {
        const float4 p = __ldcs((const float4*)&g_part[(base + c) * DD + tid * 4]);
        s.x += p.x; s.y += p.y; s.z += p.z; s.w += p.w;
        cnt += g_pcnt[base + c];
    }
    const float inv = (cnt > 0.f) ? (1.0f / cnt) : 0.0f;
    s.x *= inv; s.y *= inv; s.z *= inv; s.w *= inv;
    *(float4*)&g_means[((size_t)g * BB + b) * DD + tid * 4] = s;
}

// =====================================================================
// K3: split-K GEMM, thread = 4b x 4o (w4 reused 4x).
// Grid (G=8, 8 o-tiles, 16 d-tiles) = 1024 blocks, 128 thr.
// =====================================================================
__global__ void __launch_bounds__(128, 8) k_gemm3(const float* __restrict__ Wt) {
    __shared__ __align__(16) float w_s[K3D * K3O];     // 32 x 64 = 8 KB
    __shared__ __align__(16) float mean_s[BB * MP3];   // 32 x 32 (pitch 36) = 4.6 KB

    const int tid   = threadIdx.x;
    const int g     = blockIdx.x;
    const int obase = blockIdx.y * K3O;
    const int dq    = blockIdx.z;
    const int dbase = dq * K3D;

    const float* msrc = &g_means[(size_t)g * BB * DD + dbase];
    const float* wsrc = Wt + ((size_t)g * DD + dbase) * OUTD + obase;

    // stage W tile: 512 float4, 4 per thread (16 float4 per 64-col row)
#pragma unroll
    for (int k = 0; k < 4; k++) {
        const int i   = tid + k * 128;
        const int row = i >> 4;
        const int col = (i & 15) * 4;
        const float4 v = *(const float4*)(wsrc + (size_t)row * OUTD + col);
        *(float4*)&w_s[row * K3O + col] = v;
    }
    // stage mean tile: 256 float4, 2 per thread (8 float4 per 32-float row)
#pragma unroll
    for (int k = 0; k < 2; k++) {
        const int i  = tid + k * 128;
        const int bi = i >> 3;
        const int du = (i & 7) * 4;
        const float4 v = *(const float4*)(msrc + (size_t)bi * DD + du);
        *(float4*)&mean_s[bi * MP3 + du] = v;
    }
    __syncthreads();

    const int ocol  = (tid & 15) * 4;      // 16 lanes x float4 = 64 cols
    const int brow0 = (tid >> 4) * 4;      // 8 x 4 = 32 rows

    float4 a0 = make_float4(0.f, 0.f, 0.f, 0.f);
    float4 a1 = make_float4(0.f, 0.f, 0.f, 0.f);
    float4 a2 = make_float4(0.f, 0.f, 0.f, 0.f);
    float4 a3 = make_float4(0.f, 0.f, 0.f, 0.f);

    const float* m0 = &mean_s[brow0 * MP3];

#pragma unroll
    for (int d = 0; d < K3D; d++) {
        const float4 w4 = *(const float4*)&w_s[d * K3O + ocol];
        const float x0 = m0[d];
        const float x1 = m0[MP3 + d];
        const float x2 = m0[2 * MP3 + d];
        const float x3 = m0[3 * MP3 + d];
        a0.x = fmaf(x0, w4.x, a0.x); a0.y = fmaf(x0, w4.y, a0.y);
        a0.z = fmaf(x0, w4.z, a0.z); a0.w = fmaf(x0, w4.w, a0.w);
        a1.x = fmaf(x1, w4.x, a1.x); a1.y = fmaf(x1, w4.y, a1.y);
        a1.z = fmaf(x1, w4.z, a1.z); a1.w = fmaf(x1, w4.w, a1.w);
        a2.x = fmaf(x2, w4.x, a2.x); a2.y = fmaf(x2, w4.y, a2.y);
        a2.z = fmaf(x2, w4.z, a2.z); a2.w = fmaf(x2, w4.w, a2.w);
        a3.x = fmaf(x3, w4.x, a3.x); a3.y = fmaf(x3, w4.y, a3.y);
        a3.z = fmaf(x3, w4.z, a3.z); a3.w = fmaf(x3, w4.w, a3.w);
    }

    const int o = obase + ocol;
    float* pp = &g_ppart[(((size_t)dq * BB + brow0) * GG + g) * OUTD + o];
    *(float4*)(pp)                         = a0;
    *(float4*)(pp + (size_t)GG * OUTD)     = a1;
    *(float4*)(pp + (size_t)2 * GG * OUTD) = a2;
    *(float4*)(pp + (size_t)3 * GG * OUTD) = a3;
}

// =====================================================================
// K4: reduce split-K partials + bias -> out. Grid (B, G) = 256 blocks.
// Deterministic ascending dq order.
// =====================================================================
__global__ void __launch_bounds__(128) k_out(const float* __restrict__ bias,
                                             float* __restrict__ out) {
    const int b = blockIdx.x, g = blockIdx.y, tid = threadIdx.x;
    const int o = tid * 4;

    float4 s = *(const float4*)(bias + g * OUTD + o);
#pragma unroll
    for (int dq = 0; dq < K3_ND; dq++) {
        const float4 p = __ldcs((const float4*)&g_ppart[(((size_t)dq * BB + b) * GG + g) * OUTD + o]);
        s.x += p.x; s.y += p.y; s.z += p.z; s.w += p.w;
    }
    *(float4*)(out + ((size_t)b * GG + g) * OUTD + o) = s;
}

// =====================================================================
// Launch
// =====================================================================
extern "C" void kernel_launch(void* const* d_in, const int* in_sizes, int n_in,
                              void* d_out, int out_size) {
    const float* batch = (const float*)d_in[0];
    const float* Wt    = (const float*)d_in[1];
    const float* bias  = (const float*)d_in[2];
    const int*   types = (const int*)d_in[3];
    const int*   mask  = (const int*)d_in[4];   // bool upcast to int32: nonzero = padded
    float*       out   = (float*)d_out;

    (void)in_sizes; (void)n_in; (void)out_size;

    k_partial<<<dim3(BB, NCHUNK), 128>>>(batch, mask, types);
    k_means<<<dim3(BB, GG), 128>>>();
    k_gemm3<<<dim3(GG, OUTD / K3O, K3_ND), 128>>>(Wt);
    k_out<<<dim3(BB, GG), 128>>>(bias, out);
}